// round 8
// baseline (speedup 1.0000x reference)
#include <cuda_runtime.h>

#define A_N 5625
#define SORT_N 8192
#define M_TOT 1250
#define M_PAD 1280
#define K_TOT 4608
#define KP 2304              // K/2 pairs
#define N_TOT 512
#define NW 88
#define NDIG 6
#define KSPLIT 8
#define KCHUNK 576

typedef unsigned long long u64;
typedef unsigned u32;

// ---------------- scratch (device globals; no runtime allocation) ----------
__device__ float g_A[M_TOT * K_TOT];
__device__ float g_Bt[K_TOT * N_TOT];                      // fallback only
__device__ float2 g_psum[KSPLIT * M_TOT * N_TOT];          // fallback only
__device__ __align__(16) u32 g_Adi[(size_t)M_PAD * KP * NDIG];  // bf16x2 digit planes
__device__ __align__(16) u32 g_Bdi[(size_t)N_TOT * KP * NDIG];
__device__ int g_eA[M_PAD];
__device__ int g_eB[N_TOT];
__device__ int g_bad;
__device__ float g_h[M_TOT * N_TOT];
__device__ float g_so[M_TOT * 45];
__device__ float4 g_boxes[2 * A_N];
__device__ float g_probs[2 * A_N];
__device__ u64 g_keys[2 * A_N];
__device__ float4 g_sbox[2 * A_N];
__device__ int g_nvalid[2];
__device__ u64 g_nmsmask[2 * A_N * NW];

// ---------------- im2col with SAME zero padding (+ g_bad reset) -------------
__global__ void im2col_k(const float* __restrict__ x) {
    int e = blockIdx.x * 256 + threadIdx.x;
    if (e == 0) g_bad = 0;
    if (e >= M_TOT * K_TOT) return;
    int m = e / K_TOT, k = e - m * K_TOT;
    int b = m / 625, p = m - b * 625;
    int y = p / 25, xx = p - y * 25;
    int ci = k / 9, r = k - ci * 9;
    int ky = r / 3, kx = r - ky * 3;
    int iy = y + ky - 1, ix = xx + kx - 1;
    float v = 0.f;
    if (iy >= 0 && iy < 25 && ix >= 0 && ix < 25)
        v = x[((size_t)(b * 512 + ci) * 25 + iy) * 25 + ix];
    g_A[e] = v;
}

// ---------------- per-row |max| -> power-of-2 exponent (|scaled| < 32) ------
__global__ void rowmax_e(const float* __restrict__ src, int* __restrict__ eOut) {
    int m = blockIdx.x;
    const float* row = src + (size_t)m * K_TOT;
    float mx = 0.f;
    for (int k = threadIdx.x; k < K_TOT; k += 256) mx = fmaxf(mx, fabsf(row[k]));
    __shared__ float sm[256];
    sm[threadIdx.x] = mx;
    __syncthreads();
    for (int s = 128; s > 0; s >>= 1) {
        if (threadIdx.x < s) sm[threadIdx.x] = fmaxf(sm[threadIdx.x], sm[threadIdx.x + s]);
        __syncthreads();
    }
    if (threadIdx.x == 0) {
        int ex = 0;
        frexpf(sm[0], &ex);
        eOut[m] = ex - 5;            // scaled |val| < 32
    }
}

// ---------------- base-64 digit extraction into bf16x2 interleaved planes ---
// layout: u32 dst[(row*KP + kp)*6 + dig] = {lo=bf16(digit at k=2kp), hi=k=2kp+1}
__global__ void extract_digits6(const float* __restrict__ src, const int* __restrict__ eRow,
                                u32* __restrict__ dst, int rows_data, int rows_total) {
    int idx = blockIdx.x * 256 + threadIdx.x;
    if (idx >= rows_total * KP) return;
    int m = idx / KP, kp = idx - m * KP;
    u32* o = dst + (size_t)idx * NDIG;
    if (m >= rows_data) {
#pragma unroll
        for (int l = 0; l < NDIG; l++) o[l] = 0u;
        return;
    }
    float2 v2 = *(const float2*)(src + (size_t)m * K_TOT + kp * 2);
    float sc = __int_as_float((127 - eRow[m]) << 23);   // 2^-e
    float va = v2.x * sc, vb = v2.y * sc;
    const float MAGIC = 12582912.f;                     // 1.5 * 2^23, RNE trick
#pragma unroll
    for (int l = 0; l < NDIG; l++) {
        float ra = __fadd_rn(__fadd_rn(va, MAGIC), -MAGIC);
        float rb = __fadd_rn(__fadd_rn(vb, MAGIC), -MAGIC);
        u32 pk;
        asm("cvt.rn.bf16x2.f32 %0, %1, %2;" : "=r"(pk) : "f"(rb), "f"(ra)); // {hi=rb, lo=ra}
        o[l] = pk;
        va = __fmul_rn(__fsub_rn(va, ra), 64.f);        // exact
        vb = __fmul_rn(__fsub_rn(vb, rb), 64.f);
    }
}

// ---------------- HMMA bf16 GEMM: 21 digit-pair passes, exact fp32 accum ----
#define MMA_BF16(C, A0, A1, A2, A3, B0, B1) \
    asm volatile("mma.sync.aligned.m16n8k16.row.col.f32.bf16.bf16.f32 " \
                 "{%0,%1,%2,%3},{%4,%5,%6,%7},{%8,%9},{%0,%1,%2,%3};" \
                 : "+f"((C)[0]), "+f"((C)[1]), "+f"((C)[2]), "+f"((C)[3]) \
                 : "r"(A0), "r"(A1), "r"(A2), "r"(A3), "r"(B0), "r"(B1))

__device__ __forceinline__ void ld6(const u32* __restrict__ p, u32* d) {
    u64 x0 = *(const u64*)(p);
    u64 x1 = *(const u64*)(p + 2);
    u64 x2 = *(const u64*)(p + 4);
    d[0] = (u32)x0; d[1] = (u32)(x0 >> 32);
    d[2] = (u32)x1; d[3] = (u32)(x1 >> 32);
    d[4] = (u32)x2; d[5] = (u32)(x2 >> 32);
}

__global__ void __launch_bounds__(256) hmma_gemm(const float* __restrict__ conv_b) {
    int m0 = blockIdx.x * 64, n0 = blockIdx.y * 32;
    int wid = threadIdx.x >> 5, lane = threadIdx.x & 31;
    int wm = wid & 3, wn = wid >> 2;        // 4 m-warps x 2 n-warps
    int g = lane >> 2, t4 = lane & 3;

    int mA0 = m0 + wm * 16 + g;             // rows mA0, mA0+8
    int nB0 = n0 + wn * 16 + g;             // nt0 col g; nt1 at +8

    const u32* Ar0 = g_Adi + (size_t)mA0 * KP * NDIG;
    const u32* Ar1 = Ar0 + (size_t)8 * KP * NDIG;
    const u32* Bc0 = g_Bdi + (size_t)nB0 * KP * NDIG;
    const u32* Bc1 = Bc0 + (size_t)8 * KP * NDIG;

    float c0[NDIG][4], c1[NDIG][4];
#pragma unroll
    for (int l = 0; l < NDIG; l++)
#pragma unroll
        for (int j = 0; j < 4; j++) { c0[l][j] = 0.f; c1[l][j] = 0.f; }

    for (int kp0 = 0; kp0 < KP; kp0 += 8) {             // 16 k per step
        int plo = (kp0 + t4) * NDIG;
        int phi = (kp0 + t4 + 4) * NDIG;
        u32 A0[NDIG], A1[NDIG], A2[NDIG], A3[NDIG];     // [reg-position][dig]
        u32 B00[NDIG], B01[NDIG], B10[NDIG], B11[NDIG];
        ld6(Ar0 + plo, A0);   // (row g,   k lo)
        ld6(Ar1 + plo, A1);   // (row g+8, k lo)
        ld6(Ar0 + phi, A2);   // (row g,   k hi)
        ld6(Ar1 + phi, A3);   // (row g+8, k hi)
        ld6(Bc0 + plo, B00);  // nt0: k lo
        ld6(Bc0 + phi, B01);  //      k hi
        ld6(Bc1 + plo, B10);  // nt1
        ld6(Bc1 + phi, B11);
#pragma unroll
        for (int d = 0; d < NDIG; d++)
#pragma unroll
            for (int e = 0; e < NDIG; e++) {
                if (d + e > 5) continue;
                MMA_BF16(c0[d + e], A0[d], A1[d], A2[d], A3[d], B00[e], B01[e]);
                MMA_BF16(c1[d + e], A0[d], A1[d], A2[d], A3[d], B10[e], B11[e]);
            }
    }

    // epilogue: h = relu(2^(eA+eB) * sum_l S_l * 64^-l + bias)
#pragma unroll
    for (int nt = 0; nt < 2; nt++) {
        float (*cc)[4] = nt ? c1 : c0;
        int nbase = n0 + wn * 16 + nt * 8 + t4 * 2;
#pragma unroll
        for (int j = 0; j < 4; j++) {
            int m = mA0 + ((j >> 1) ? 8 : 0);
            int n = nbase + (j & 1);
            if (m >= M_TOT) continue;
            double s = 0.0;
#pragma unroll
            for (int l = 0; l < NDIG; l++)
                s += ldexp((double)cc[l][j], -6 * l);
            s = ldexp(s, g_eA[m] + g_eB[n]);
            float h = (float)(s + (double)conv_b[n]);
            g_h[(size_t)m * N_TOT + n] = fmaxf(h, 0.f);
        }
    }
}

// ---------------- probe: verify 256 entries of g_h --------------------------
__global__ void probe_check(const float* __restrict__ w, const float* __restrict__ conv_b) {
    int gw = blockIdx.x * 8 + (threadIdx.x >> 5);
    int lane = threadIdx.x & 31;
    int m = (gw * 131 + 7) % M_TOT;
    int n = (gw * 37 + 3) % N_TOT;
    const float* arow = g_A + (size_t)m * K_TOT;
    const float* brow = w + (size_t)n * K_TOT;
    float s = 0.f, lo = 0.f;
    for (int k = lane; k < K_TOT; k += 32) {
        float a = arow[k], b = brow[k];
        float p = a * b;
        float e = __fmaf_rn(a, b, -p);
        float t = s + p;
        float z = t - s;
        lo += ((p - z) + e);
        s = t;
    }
    double d = (double)s + (double)lo;
#pragma unroll
    for (int off = 16; off > 0; off >>= 1)
        d += __shfl_down_sync(0xffffffffu, d, off);
    if (lane == 0) {
        float ref = fmaxf((float)(d + (double)conv_b[n]), 0.f);
        float got = g_h[(size_t)m * N_TOT + n];
        float tol = 1e-3f * (1.f + fabsf(ref));
        if (!(fabsf(got - ref) <= tol)) atomicExch(&g_bad, 1);
    }
}

// ---------------- FALLBACK path (early-exits when HMMA verified) -----------
__global__ void transpose_w(const float* __restrict__ w) {
    if (g_bad == 0) return;
    __shared__ float sh[32][33];
    int k0 = blockIdx.x * 32, n0 = blockIdx.y * 32;
    int tx = threadIdx.x, ty = threadIdx.y;
    sh[ty][tx] = w[(size_t)(n0 + ty) * K_TOT + k0 + tx];
    __syncthreads();
    g_Bt[(size_t)(k0 + ty) * N_TOT + n0 + tx] = sh[tx][ty];
}

__global__ void __launch_bounds__(256) conv_gemm_df() {
    if (g_bad == 0) return;
    __shared__ float As[16][68];
    __shared__ float Bs[16][64];
    int m0 = blockIdx.x * 64;
    int n0 = blockIdx.y * 64;
    int zz = blockIdx.z;
    int kbase = zz * KCHUNK;
    int tid = threadIdx.x;
    int tr = tid >> 4, tc = tid & 15;

    float s[4][4], lo[4][4];
#pragma unroll
    for (int r = 0; r < 4; r++)
#pragma unroll
        for (int c = 0; c < 4; c++) { s[r][c] = 0.f; lo[r][c] = 0.f; }

    int ar = tid >> 2, aq = (tid & 3) * 4;
    int bk = tid >> 4, bn = (tid & 15) * 4;

    const float* Ab = g_A + (size_t)m0 * K_TOT + kbase;
    const float* Bb = g_Bt + (size_t)kbase * N_TOT + n0;
    bool arow_ok = (m0 + ar) < M_TOT;

    for (int k0 = 0; k0 < KCHUNK; k0 += 16) {
        float4 ra = arow_ok ? *(const float4*)(Ab + (size_t)ar * K_TOT + k0 + aq)
                            : make_float4(0.f, 0.f, 0.f, 0.f);
        float4 rb = *(const float4*)(Bb + (size_t)(k0 + bk) * N_TOT + bn);
        __syncthreads();
        As[aq + 0][ar] = ra.x; As[aq + 1][ar] = ra.y;
        As[aq + 2][ar] = ra.z; As[aq + 3][ar] = ra.w;
        *(float4*)&Bs[bk][bn] = rb;
        __syncthreads();

#pragma unroll
        for (int ks = 0; ks < 16; ks++) {
            float4 a = *(float4*)&As[ks][tr * 4];
            float4 b = *(float4*)&Bs[ks][tc * 4];
            float av[4] = {a.x, a.y, a.z, a.w};
            float bv[4] = {b.x, b.y, b.z, b.w};
#pragma unroll
            for (int r = 0; r < 4; r++)
#pragma unroll
                for (int c = 0; c < 4; c++) {
                    float p = av[r] * bv[c];
                    float e = __fmaf_rn(av[r], bv[c], -p);
                    float t = s[r][c] + p;
                    float z = t - s[r][c];
                    float err = p - z;
                    s[r][c] = t;
                    lo[r][c] += (err + e);
                }
        }
    }

    float2* Co = g_psum + (size_t)zz * (M_TOT * N_TOT);
#pragma unroll
    for (int r = 0; r < 4; r++) {
        int m = m0 + tr * 4 + r;
        if (m < M_TOT) {
#pragma unroll
            for (int c = 0; c < 4; c++) {
                int n = n0 + tc * 4 + c;
                Co[(size_t)m * N_TOT + n] = make_float2(s[r][c], lo[r][c]);
            }
        }
    }
}

__global__ void reduce_relu(const float* __restrict__ conv_b) {
    if (g_bad == 0) return;
    int i = blockIdx.x * 256 + threadIdx.x;
    if (i >= M_TOT * N_TOT) return;
    int n = i & (N_TOT - 1);
    double acc = (double)conv_b[n];
#pragma unroll
    for (int z = 0; z < KSPLIT; z++) {
        float2 v = g_psum[(size_t)z * (M_TOT * N_TOT) + i];
        acc += (double)v.x + (double)v.y;
    }
    g_h[i] = fmaxf((float)acc, 0.f);
}

// ---------------- head dots: one warp per (m, o), compensated fp32 ---------
__global__ void heads_dots(const float* __restrict__ reg_w, const float* __restrict__ reg_b,
                           const float* __restrict__ cls_w, const float* __restrict__ cls_b) {
    int gw = (blockIdx.x * 256 + threadIdx.x) >> 5;
    int lane = threadIdx.x & 31;
    if (gw >= M_TOT * 45) return;
    int m = gw / 45, o = gw - m * 45;
    const float* w = (o < 36) ? (reg_w + (size_t)o * 512) : (cls_w + (size_t)(o - 36) * 512);
    float bias = (o < 36) ? reg_b[o] : cls_b[o - 36];
    const float* hrow = g_h + (size_t)m * 512;
    float s = 0.f, lo = 0.f;
#pragma unroll
    for (int j = 0; j < 16; j++) {
        int idx = lane + 32 * j;
        float a = hrow[idx], b = __ldg(w + idx);
        float p = a * b;
        float e = __fmaf_rn(a, b, -p);
        float t = s + p;
        float z = t - s;
        float err = p - z;
        s = t;
        lo += (err + e);
    }
    double d = (double)s + (double)lo;
#pragma unroll
    for (int off = 16; off > 0; off >>= 1)
        d += __shfl_down_sync(0xffffffffu, d, off);
    if (lane == 0) g_so[gw] = (float)(d + (double)bias);
}

// ---------------- decode boxes + probs + sort keys -------------------------
__global__ void decode_keys(const float* __restrict__ anchors) {
    int i = blockIdx.x * 256 + threadIdx.x;
    if (i >= M_TOT * 9) return;
    int m = i / 9, t9 = i - m * 9;
    const float* so = g_so + (size_t)m * 45;
    int b = m / 625, p = m - b * 625;
    int a = p * 9 + t9;
    float4 anc = ((const float4*)anchors)[a];
    float acx = (anc.x + anc.z) * 0.5f, acy = (anc.y + anc.w) * 0.5f;
    float aw = anc.z - anc.x, ah = anc.w - anc.y;
    float ox = so[t9 * 4 + 0], oy = so[t9 * 4 + 1];
    float ow = so[t9 * 4 + 2], oh = so[t9 * 4 + 3];
    float cx = ox * aw / 10.0f + acx;
    float cy = oy * ah / 10.0f + acy;
    float bw = expf(ow / 5.0f) * aw;
    float bh = expf(oh / 5.0f) * ah;
    float4 box = make_float4(cx - bw * 0.5f, cy - bh * 0.5f, cx + bw * 0.5f, cy + bh * 0.5f);
    float logit = so[36 + t9];
    float prob = 1.0f / (1.0f + expf(-logit));
    int gi = b * A_N + a;
    g_boxes[gi] = box;
    g_probs[gi] = prob;
    float keyf = (prob > 0.5f) ? prob : -1.0f;
    unsigned u = __float_as_uint(keyf);
    u = (u & 0x80000000u) ? ~u : (u | 0x80000000u);
    g_keys[gi] = ((u64)(~u) << 32) | (unsigned)a;
}

// ---------------- per-image stable bitonic sort + gather -------------------
__global__ void __launch_bounds__(1024) sort_pass(float* __restrict__ out) {
    extern __shared__ u64 arr[];
    int b = blockIdx.x;
    int tid = threadIdx.x;

    if (tid == 0) g_nvalid[b] = 0;
    for (int i = tid; i < SORT_N; i += 1024)
        arr[i] = (i < A_N) ? g_keys[b * A_N + i] : 0xFFFFFFFFFFFFFFFFull;
    __syncthreads();

    for (int k = 2; k <= SORT_N; k <<= 1) {
        for (int j = k >> 1; j > 0; j >>= 1) {
            for (int i = tid; i < SORT_N; i += 1024) {
                int ixj = i ^ j;
                if (ixj > i) {
                    u64 u = arr[i], v = arr[ixj];
                    bool up = (i & k) == 0;
                    if ((u > v) == up) { arr[i] = v; arr[ixj] = u; }
                }
            }
            __syncthreads();
        }
    }

    int cnt = 0;
    for (int i = tid; i < A_N; i += 1024) {
        unsigned idx = (unsigned)(arr[i] & 0xFFFFFFFFu);
        float4 bx = g_boxes[b * A_N + idx];
        float p = g_probs[b * A_N + idx];
        g_sbox[b * A_N + i] = bx;
        float* o = out + (size_t)(b * A_N + i) * 6;
        o[0] = bx.x; o[1] = bx.y; o[2] = bx.z; o[3] = bx.w; o[4] = p;
        if (p > 0.5f) cnt++;
    }
    atomicAdd(&g_nvalid[b], cnt);
}

// ---------------- IoU bit matrix ---------------------------------------------
__global__ void __launch_bounds__(256) iou_mask() {
    extern __shared__ float4 sb[];
    int b = blockIdx.y;
    int nv = g_nvalid[b];
    int r0 = blockIdx.x * 128;
    if (r0 >= nv) return;
    int tid = threadIdx.x;
    int wid = tid >> 5, lane = tid & 31;

    for (int i = tid; i < A_N; i += 256) sb[i] = g_sbox[b * A_N + i];
    __syncthreads();

#pragma unroll 1
    for (int rr = 0; rr < 16; rr++) {
        int i = r0 + wid * 16 + rr;
        if (i >= nv) continue;
        float4 bi = sb[i];
        float ai = (bi.z - bi.x) * (bi.w - bi.y);
        u64* row = g_nmsmask + ((size_t)b * A_N + i) * NW;
#pragma unroll 1
        for (int w = 0; w < NW; w++) {
            int j0 = w * 64 + lane;
            int j1 = j0 + 32;
            bool p0 = false, p1 = false;
            if (j0 < A_N && j0 != i) {
                float4 bj = sb[j0];
                float iw = fminf(bi.z, bj.z) - fmaxf(bi.x, bj.x);
                float ih = fminf(bi.w, bj.w) - fmaxf(bi.y, bj.y);
                float inter = fmaxf(iw, 0.f) * fmaxf(ih, 0.f);
                float aj = (bj.z - bj.x) * (bj.w - bj.y);
                p0 = inter / (ai + aj - inter) > 0.5f;
            }
            if (j1 < A_N && j1 != i) {
                float4 bj = sb[j1];
                float iw = fminf(bi.z, bj.z) - fmaxf(bi.x, bj.x);
                float ih = fminf(bi.w, bj.w) - fmaxf(bi.y, bj.y);
                float inter = fmaxf(iw, 0.f) * fmaxf(ih, 0.f);
                float aj = (bj.z - bj.x) * (bj.w - bj.y);
                p1 = inter / (ai + aj - inter) > 0.5f;
            }
            unsigned m0 = __ballot_sync(0xffffffffu, p0);
            unsigned m1 = __ballot_sync(0xffffffffu, p1);
            if (lane == 0) row[w] = (u64)m0 | ((u64)m1 << 32);
        }
    }
}

// ---------------- serial greedy scan: one warp per image -------------------
#define PF 8
__global__ void __launch_bounds__(32) nms_scan(float* __restrict__ out) {
    int b = blockIdx.x;
    int lane = threadIdx.x;
    int nv = g_nvalid[b];
    const u64* base = g_nmsmask + (size_t)b * A_N * NW;

    int w0 = lane, w1 = lane + 32, w2 = lane + 64;
    bool has2 = w2 < NW;
    u64 rm0 = 0, rm1 = 0, rm2 = 0;

    u64 buf[PF][3];
#pragma unroll
    for (int d = 0; d < PF; d++) {
        if (d < nv) {
            const u64* r = base + (size_t)d * NW;
            buf[d][0] = __ldg(r + w0);
            buf[d][1] = __ldg(r + w1);
            buf[d][2] = has2 ? __ldg(r + w2) : 0ull;
        } else { buf[d][0] = buf[d][1] = buf[d][2] = 0ull; }
    }

    for (int i0 = 0; i0 < nv; i0 += PF) {
#pragma unroll
        for (int d = 0; d < PF; d++) {
            int i = i0 + d;
            if (i >= nv) break;
            u64 c0 = buf[d][0], c1 = buf[d][1], c2 = buf[d][2];
            int ip = i + PF;
            if (ip < nv) {
                const u64* r = base + (size_t)ip * NW;
                buf[d][0] = __ldg(r + w0);
                buf[d][1] = __ldg(r + w1);
                buf[d][2] = has2 ? __ldg(r + w2) : 0ull;
            }
            int w = i >> 6;
            int owner = w & 31, slot = w >> 5;
            u64 myw = (slot == 0) ? rm0 : ((slot == 1) ? rm1 : rm2);
            u64 vw = __shfl_sync(0xffffffffu, myw, owner);
            if (!((vw >> (i & 63)) & 1ull)) {
                rm0 |= c0; rm1 |= c1; if (has2) rm2 |= c2;
            }
        }
    }

#pragma unroll
    for (int s = 0; s < 3; s++) {
        int w = lane + 32 * s;
        if (w >= NW) break;
        u64 r = (s == 0) ? rm0 : ((s == 1) ? rm1 : rm2);
        for (int t = 0; t < 64; t++) {
            int i = w * 64 + t;
            if (i < A_N)
                out[(size_t)(b * A_N + i) * 6 + 5] =
                    (i < nv && !((r >> t) & 1ull)) ? 1.f : 0.f;
        }
    }
}

// ---------------- launch ----------------------------------------------------
extern "C" void kernel_launch(void* const* d_in, const int* in_sizes, int n_in,
                              void* d_out, int out_size) {
    const float* x      = (const float*)d_in[0];
    const float* conv_w = (const float*)d_in[1];
    const float* conv_b = (const float*)d_in[2];
    const float* reg_w  = (const float*)d_in[3];
    const float* reg_b  = (const float*)d_in[4];
    const float* cls_w  = (const float*)d_in[5];
    const float* cls_b  = (const float*)d_in[6];
    const float* anchors = (const float*)d_in[7];
    float* out = (float*)d_out;

    im2col_k<<<(M_TOT * K_TOT + 255) / 256, 256>>>(x);
    rowmax_e<<<M_TOT, 256>>>(g_A, g_eA);
    rowmax_e<<<N_TOT, 256>>>(conv_w, g_eB);
    extract_digits6<<<(M_PAD * KP + 255) / 256, 256>>>(g_A, g_eA, g_Adi, M_TOT, M_PAD);
    extract_digits6<<<(N_TOT * KP + 255) / 256, 256>>>(conv_w, g_eB, g_Bdi, N_TOT, N_TOT);
    hmma_gemm<<<dim3(M_PAD / 64, N_TOT / 32), 256>>>(conv_b);
    probe_check<<<32, 256>>>(conv_w, conv_b);

    // fallback chain (early-exits when probe says HMMA is good)
    transpose_w<<<dim3(K_TOT / 32, N_TOT / 32), dim3(32, 32)>>>(conv_w);
    conv_gemm_df<<<dim3(20, 8, KSPLIT), 256>>>();
    reduce_relu<<<(M_TOT * N_TOT + 255) / 256, 256>>>(conv_b);

    heads_dots<<<(M_TOT * 45 * 32 + 255) / 256, 256>>>(reg_w, reg_b, cls_w, cls_b);
    decode_keys<<<(M_TOT * 9 + 255) / 256, 256>>>(anchors);

    static int attr_done = 0;
    if (!attr_done) {
        cudaFuncSetAttribute(sort_pass, cudaFuncAttributeMaxDynamicSharedMemorySize, SORT_N * 8);
        cudaFuncSetAttribute(iou_mask, cudaFuncAttributeMaxDynamicSharedMemorySize, A_N * 16);
        attr_done = 1;
    }
    sort_pass<<<2, 1024, SORT_N * 8>>>(out);
    iou_mask<<<dim3(44, 2), 256, A_N * 16>>>();
    nms_scan<<<2, 32>>>(out);
}

// round 10
// speedup vs baseline: 4.0246x; 4.0246x over previous
#include <cuda_runtime.h>

#define A_N 5625
#define SORT_N 8192
#define M_TOT 1250
#define K_TOT 4608
#define N_TOT 512
#define KSPLIT 8
#define KCHUNK 576           // 4608 / 8
#define NW 88                // mask words per row (88*64 = 5632 >= 5625)

typedef unsigned long long u64;

// ---------------- scratch (device globals; no runtime allocation) ----------
__device__ float g_A[M_TOT * K_TOT];
__device__ float g_Bt[K_TOT * N_TOT];
__device__ float2 g_psum[KSPLIT * M_TOT * N_TOT];
__device__ float g_h[M_TOT * N_TOT];
__device__ float g_so[M_TOT * 45];
__device__ float4 g_boxes[2 * A_N];
__device__ float g_probs[2 * A_N];
__device__ u64 g_keys[2 * A_N];
__device__ float4 g_sbox[2 * A_N];
__device__ int g_nvalid[2];
__device__ u64 g_nmsmask[2 * A_N * NW];

// ---------------- weight transpose: Bt[k][n] = w[n][k] ---------------------
__global__ void transpose_w(const float* __restrict__ w) {
    __shared__ float sh[32][33];
    int k0 = blockIdx.x * 32, n0 = blockIdx.y * 32;
    int tx = threadIdx.x, ty = threadIdx.y;
    sh[ty][tx] = w[(size_t)(n0 + ty) * K_TOT + k0 + tx];
    __syncthreads();
    g_Bt[(size_t)(k0 + ty) * N_TOT + n0 + tx] = sh[tx][ty];
}

// ---------------- im2col with SAME zero padding -----------------------------
__global__ void im2col_k(const float* __restrict__ x) {
    int e = blockIdx.x * 256 + threadIdx.x;
    if (e >= M_TOT * K_TOT) return;
    int m = e / K_TOT, k = e - m * K_TOT;
    int b = m / 625, p = m - b * 625;
    int y = p / 25, xx = p - y * 25;
    int ci = k / 9, r = k - ci * 9;
    int ky = r / 3, kx = r - ky * 3;
    int iy = y + ky - 1, ix = xx + kx - 1;
    float v = 0.f;
    if (iy >= 0 && iy < 25 && ix >= 0 && ix < 25)
        v = x[((size_t)(b * 512 + ci) * 25 + iy) * 25 + ix];
    g_A[e] = v;
}

// ---------------- conv GEMM: 4-op FMA-Kahan compensated fp32 ---------------
// t = fma(a,b,s); z = t-s; err = fma(a,b,-z); lo += err.
// Product enters fma exactly; Sterbenz makes z exact in steady state.
__global__ void __launch_bounds__(256) conv_gemm_k4() {
    __shared__ float As[16][68];
    __shared__ float Bs[16][64];
    int m0 = blockIdx.x * 64;
    int n0 = blockIdx.y * 64;
    int zz = blockIdx.z;
    int kbase = zz * KCHUNK;
    int tid = threadIdx.x;
    int tr = tid >> 4, tc = tid & 15;

    float s[4][4], lo[4][4];
#pragma unroll
    for (int r = 0; r < 4; r++)
#pragma unroll
        for (int c = 0; c < 4; c++) { s[r][c] = 0.f; lo[r][c] = 0.f; }

    int ar = tid >> 2, aq = (tid & 3) * 4;   // A: 64 rows x 16 k
    int bk = tid >> 4, bn = (tid & 15) * 4;  // B: 16 k x 64 n

    const float* Ab = g_A + (size_t)m0 * K_TOT + kbase;
    const float* Bb = g_Bt + (size_t)kbase * N_TOT + n0;
    bool arow_ok = (m0 + ar) < M_TOT;

    for (int k0 = 0; k0 < KCHUNK; k0 += 16) {
        float4 ra = arow_ok ? *(const float4*)(Ab + (size_t)ar * K_TOT + k0 + aq)
                            : make_float4(0.f, 0.f, 0.f, 0.f);
        float4 rb = *(const float4*)(Bb + (size_t)(k0 + bk) * N_TOT + bn);
        __syncthreads();
        As[aq + 0][ar] = ra.x; As[aq + 1][ar] = ra.y;
        As[aq + 2][ar] = ra.z; As[aq + 3][ar] = ra.w;
        *(float4*)&Bs[bk][bn] = rb;
        __syncthreads();

#pragma unroll
        for (int ks = 0; ks < 16; ks++) {
            float4 a = *(float4*)&As[ks][tr * 4];
            float4 b = *(float4*)&Bs[ks][tc * 4];
            float av[4] = {a.x, a.y, a.z, a.w};
            float bv[4] = {b.x, b.y, b.z, b.w};
#pragma unroll
            for (int r = 0; r < 4; r++)
#pragma unroll
                for (int c = 0; c < 4; c++) {
                    float t   = __fmaf_rn(av[r], bv[c], s[r][c]);
                    float z   = __fsub_rn(t, s[r][c]);
                    float err = __fmaf_rn(av[r], bv[c], -z);
                    s[r][c]   = t;
                    lo[r][c]  = __fadd_rn(lo[r][c], err);
                }
        }
    }

    float2* Co = g_psum + (size_t)zz * (M_TOT * N_TOT);
#pragma unroll
    for (int r = 0; r < 4; r++) {
        int m = m0 + tr * 4 + r;
        if (m < M_TOT) {
#pragma unroll
            for (int c = 0; c < 4; c++) {
                int n = n0 + tc * 4 + c;
                Co[(size_t)m * N_TOT + n] = make_float2(s[r][c], lo[r][c]);
            }
        }
    }
}

// ---------------- reduce split-K double-float slabs + bias + relu ----------
__global__ void reduce_relu(const float* __restrict__ conv_b) {
    int i = blockIdx.x * 256 + threadIdx.x;
    if (i >= M_TOT * N_TOT) return;
    int n = i & (N_TOT - 1);
    double acc = (double)conv_b[n];
#pragma unroll
    for (int z = 0; z < KSPLIT; z++) {
        float2 v = g_psum[(size_t)z * (M_TOT * N_TOT) + i];
        acc += (double)v.x + (double)v.y;
    }
    g_h[i] = fmaxf((float)acc, 0.f);
}

// ---------------- head dots: one warp per (m, o), compensated fp32 ---------
__global__ void heads_dots(const float* __restrict__ reg_w, const float* __restrict__ reg_b,
                           const float* __restrict__ cls_w, const float* __restrict__ cls_b) {
    int gw = (blockIdx.x * 256 + threadIdx.x) >> 5;
    int lane = threadIdx.x & 31;
    if (gw >= M_TOT * 45) return;
    int m = gw / 45, o = gw - m * 45;
    const float* w = (o < 36) ? (reg_w + (size_t)o * 512) : (cls_w + (size_t)(o - 36) * 512);
    float bias = (o < 36) ? reg_b[o] : cls_b[o - 36];
    const float* hrow = g_h + (size_t)m * 512;
    float s = 0.f, lo = 0.f;
#pragma unroll
    for (int j = 0; j < 16; j++) {
        int idx = lane + 32 * j;
        float a = hrow[idx], b = __ldg(w + idx);
        float p = __fmul_rn(a, b);
        float e = __fmaf_rn(a, b, -p);
        float t = __fadd_rn(s, p);
        float z = __fsub_rn(t, s);
        float err = __fsub_rn(p, z);
        s = t;
        lo = __fadd_rn(lo, __fadd_rn(err, e));
    }
    double d = (double)s + (double)lo;
#pragma unroll
    for (int off = 16; off > 0; off >>= 1)
        d += __shfl_down_sync(0xffffffffu, d, off);
    if (lane == 0) g_so[gw] = (float)(d + (double)bias);
}

// ---------------- decode boxes + probs + sort keys -------------------------
__global__ void decode_keys(const float* __restrict__ anchors) {
    int i = blockIdx.x * 256 + threadIdx.x;
    if (i >= M_TOT * 9) return;
    int m = i / 9, t9 = i - m * 9;
    const float* so = g_so + (size_t)m * 45;
    int b = m / 625, p = m - b * 625;
    int a = p * 9 + t9;
    float4 anc = ((const float4*)anchors)[a];
    float acx = (anc.x + anc.z) * 0.5f, acy = (anc.y + anc.w) * 0.5f;
    float aw = anc.z - anc.x, ah = anc.w - anc.y;
    float ox = so[t9 * 4 + 0], oy = so[t9 * 4 + 1];
    float ow = so[t9 * 4 + 2], oh = so[t9 * 4 + 3];
    float cx = ox * aw / 10.0f + acx;
    float cy = oy * ah / 10.0f + acy;
    float bw = expf(ow / 5.0f) * aw;
    float bh = expf(oh / 5.0f) * ah;
    float4 box = make_float4(cx - bw * 0.5f, cy - bh * 0.5f, cx + bw * 0.5f, cy + bh * 0.5f);
    float logit = so[36 + t9];
    float prob = 1.0f / (1.0f + expf(-logit));
    int gi = b * A_N + a;
    g_boxes[gi] = box;
    g_probs[gi] = prob;
    float keyf = (prob > 0.5f) ? prob : -1.0f;
    unsigned u = __float_as_uint(keyf);
    u = (u & 0x80000000u) ? ~u : (u | 0x80000000u);
    g_keys[gi] = ((u64)(~u) << 32) | (unsigned)a;
}

// ---------------- per-image stable bitonic sort + gather -------------------
__global__ void __launch_bounds__(1024) sort_pass(float* __restrict__ out) {
    extern __shared__ u64 arr[];
    int b = blockIdx.x;
    int tid = threadIdx.x;

    if (tid == 0) g_nvalid[b] = 0;
    for (int i = tid; i < SORT_N; i += 1024)
        arr[i] = (i < A_N) ? g_keys[b * A_N + i] : 0xFFFFFFFFFFFFFFFFull;
    __syncthreads();

    for (int k = 2; k <= SORT_N; k <<= 1) {
        for (int j = k >> 1; j > 0; j >>= 1) {
            for (int i = tid; i < SORT_N; i += 1024) {
                int ixj = i ^ j;
                if (ixj > i) {
                    u64 u = arr[i], v = arr[ixj];
                    bool up = (i & k) == 0;
                    if ((u > v) == up) { arr[i] = v; arr[ixj] = u; }
                }
            }
            __syncthreads();
        }
    }

    int cnt = 0;
    for (int i = tid; i < A_N; i += 1024) {
        unsigned idx = (unsigned)(arr[i] & 0xFFFFFFFFu);
        float4 bx = g_boxes[b * A_N + idx];
        float p = g_probs[b * A_N + idx];
        g_sbox[b * A_N + i] = bx;
        float* o = out + (size_t)(b * A_N + i) * 6;
        o[0] = bx.x; o[1] = bx.y; o[2] = bx.z; o[3] = bx.w; o[4] = p;
        if (p > 0.5f) cnt++;
    }
    atomicAdd(&g_nvalid[b], cnt);
}

// ---------------- IoU bit matrix ---------------------------------------------
__global__ void __launch_bounds__(256) iou_mask() {
    extern __shared__ float4 sb[];
    int b = blockIdx.y;
    int nv = g_nvalid[b];
    int r0 = blockIdx.x * 128;
    if (r0 >= nv) return;
    int tid = threadIdx.x;
    int wid = tid >> 5, lane = tid & 31;

    for (int i = tid; i < A_N; i += 256) sb[i] = g_sbox[b * A_N + i];
    __syncthreads();

#pragma unroll 1
    for (int rr = 0; rr < 16; rr++) {
        int i = r0 + wid * 16 + rr;
        if (i >= nv) continue;
        float4 bi = sb[i];
        float ai = (bi.z - bi.x) * (bi.w - bi.y);
        u64* row = g_nmsmask + ((size_t)b * A_N + i) * NW;
#pragma unroll 1
        for (int w = 0; w < NW; w++) {
            int j0 = w * 64 + lane;
            int j1 = j0 + 32;
            bool p0 = false, p1 = false;
            if (j0 < A_N && j0 != i) {
                float4 bj = sb[j0];
                float iw = fminf(bi.z, bj.z) - fmaxf(bi.x, bj.x);
                float ih = fminf(bi.w, bj.w) - fmaxf(bi.y, bj.y);
                float inter = fmaxf(iw, 0.f) * fmaxf(ih, 0.f);
                float aj = (bj.z - bj.x) * (bj.w - bj.y);
                p0 = inter / (ai + aj - inter) > 0.5f;
            }
            if (j1 < A_N && j1 != i) {
                float4 bj = sb[j1];
                float iw = fminf(bi.z, bj.z) - fmaxf(bi.x, bj.x);
                float ih = fminf(bi.w, bj.w) - fmaxf(bi.y, bj.y);
                float inter = fmaxf(iw, 0.f) * fmaxf(ih, 0.f);
                float aj = (bj.z - bj.x) * (bj.w - bj.y);
                p1 = inter / (ai + aj - inter) > 0.5f;
            }
            unsigned m0 = __ballot_sync(0xffffffffu, p0);
            unsigned m1 = __ballot_sync(0xffffffffu, p1);
            if (lane == 0) row[w] = (u64)m0 | ((u64)m1 << 32);
        }
    }
}

// ---------------- serial greedy scan: one warp per image -------------------
#define PF 8
__global__ void __launch_bounds__(32) nms_scan(float* __restrict__ out) {
    int b = blockIdx.x;
    int lane = threadIdx.x;
    int nv = g_nvalid[b];
    const u64* base = g_nmsmask + (size_t)b * A_N * NW;

    int w0 = lane, w1 = lane + 32, w2 = lane + 64;
    bool has2 = w2 < NW;
    u64 rm0 = 0, rm1 = 0, rm2 = 0;

    u64 buf[PF][3];
#pragma unroll
    for (int d = 0; d < PF; d++) {
        if (d < nv) {
            const u64* r = base + (size_t)d * NW;
            buf[d][0] = __ldg(r + w0);
            buf[d][1] = __ldg(r + w1);
            buf[d][2] = has2 ? __ldg(r + w2) : 0ull;
        } else { buf[d][0] = buf[d][1] = buf[d][2] = 0ull; }
    }

    for (int i0 = 0; i0 < nv; i0 += PF) {
#pragma unroll
        for (int d = 0; d < PF; d++) {
            int i = i0 + d;
            if (i >= nv) break;
            u64 c0 = buf[d][0], c1 = buf[d][1], c2 = buf[d][2];
            int ip = i + PF;
            if (ip < nv) {
                const u64* r = base + (size_t)ip * NW;
                buf[d][0] = __ldg(r + w0);
                buf[d][1] = __ldg(r + w1);
                buf[d][2] = has2 ? __ldg(r + w2) : 0ull;
            }
            int w = i >> 6;
            int owner = w & 31, slot = w >> 5;
            u64 myw = (slot == 0) ? rm0 : ((slot == 1) ? rm1 : rm2);
            u64 vw = __shfl_sync(0xffffffffu, myw, owner);
            if (!((vw >> (i & 63)) & 1ull)) {
                rm0 |= c0; rm1 |= c1; if (has2) rm2 |= c2;
            }
        }
    }

#pragma unroll
    for (int s = 0; s < 3; s++) {
        int w = lane + 32 * s;
        if (w >= NW) break;
        u64 r = (s == 0) ? rm0 : ((s == 1) ? rm1 : rm2);
        for (int t = 0; t < 64; t++) {
            int i = w * 64 + t;
            if (i < A_N)
                out[(size_t)(b * A_N + i) * 6 + 5] =
                    (i < nv && !((r >> t) & 1ull)) ? 1.f : 0.f;
        }
    }
}

// ---------------- launch ----------------------------------------------------
extern "C" void kernel_launch(void* const* d_in, const int* in_sizes, int n_in,
                              void* d_out, int out_size) {
    const float* x      = (const float*)d_in[0];
    const float* conv_w = (const float*)d_in[1];
    const float* conv_b = (const float*)d_in[2];
    const float* reg_w  = (const float*)d_in[3];
    const float* reg_b  = (const float*)d_in[4];
    const float* cls_w  = (const float*)d_in[5];
    const float* cls_b  = (const float*)d_in[6];
    const float* anchors = (const float*)d_in[7];
    float* out = (float*)d_out;

    transpose_w<<<dim3(K_TOT / 32, N_TOT / 32), dim3(32, 32)>>>(conv_w);
    im2col_k<<<(M_TOT * K_TOT + 255) / 256, 256>>>(x);
    conv_gemm_k4<<<dim3(20, 8, KSPLIT), 256>>>();
    reduce_relu<<<(M_TOT * N_TOT + 255) / 256, 256>>>(conv_b);
    heads_dots<<<(M_TOT * 45 * 32 + 255) / 256, 256>>>(reg_w, reg_b, cls_w, cls_b);
    decode_keys<<<(M_TOT * 9 + 255) / 256, 256>>>(anchors);

    static int attr_done = 0;
    if (!attr_done) {
        cudaFuncSetAttribute(sort_pass, cudaFuncAttributeMaxDynamicSharedMemorySize, SORT_N * 8);
        cudaFuncSetAttribute(iou_mask, cudaFuncAttributeMaxDynamicSharedMemorySize, A_N * 16);
        attr_done = 1;
    }
    sort_pass<<<2, 1024, SORT_N * 8>>>(out);
    iou_mask<<<dim3(44, 2), 256, A_N * 16>>>();
    nms_scan<<<2, 32>>>(out);
}